// round 3
// baseline (speedup 1.0000x reference)
#include <cuda_runtime.h>
#include <cstdint>

#define BB 32
#define NPTS 4096
#define S1 512
#define S2 128
#define NSAMP 64

// ---------------- scratch (static device memory; no allocation) ----------------
#define OFF_XYZ1  0                        // 32*512*3
#define OFF_FEAT1 (OFF_XYZ1 + BB*S1*3)     // 32*512*128
#define OFF_XYZ2  (OFF_FEAT1 + BB*S1*128)  // 32*128*3
#define OFF_FEAT2 (OFF_XYZ2 + BB*S2*3)     // 32*128*256
#define OFF_H31   (OFF_FEAT2 + BB*S2*256)  // 32*128*256
#define OFF_H32   (OFF_H31 + BB*S2*256)    // 32*128*512
#define FSCRATCH_TOTAL (OFF_H32 + BB*S2*512)

#define IOFF_FPS1  0
#define IOFF_BALL1 (IOFF_FPS1 + BB*S1)
#define IOFF_FPS2  (IOFF_BALL1 + BB*S1*NSAMP)
#define IOFF_BALL2 (IOFF_FPS2 + BB*S2)
#define ISCRATCH_TOTAL (IOFF_BALL2 + BB*S2*NSAMP)

__device__ float d_fscratch[FSCRATCH_TOTAL];
__device__ int   d_iscratch[ISCRATCH_TOTAL];

// ---------------- FPS ----------------
// one block per batch, 512 threads, xyz + running min-dist in smem.
// argmax with first-index tie-break via packed 64-bit key.
template<int N, int NPOINT>
__global__ void fps_kernel(const float* __restrict__ xyz,
                           int* __restrict__ oidx, float* __restrict__ octr)
{
    extern __shared__ float smf[];
    float* sx = smf;
    float* sy = smf + N;
    float* sz = smf + 2 * N;
    float* sd = smf + 3 * N;
    __shared__ unsigned long long wmax[17];

    const int b = blockIdx.x, tid = threadIdx.x;
    const float* p = xyz + (size_t)b * N * 3;

    for (int i = tid; i < N; i += 512) {
        sx[i] = p[3 * i + 0];
        sy[i] = p[3 * i + 1];
        sz[i] = p[3 * i + 2];
        sd[i] = 1e10f;
    }
    if (tid == 0) oidx[b * NPOINT] = 0;
    __syncthreads();

    int last = 0;
    for (int it = 1; it < NPOINT; ++it) {
        const float lx = sx[last], ly = sy[last], lz = sz[last];
        unsigned long long best = 0ull;
        #pragma unroll
        for (int i = tid; i < N; i += 512) {
            float dx = sx[i] - lx, dy = sy[i] - ly, dz = sz[i] - lz;
            // exact reference arithmetic: (x*x + y*y) + z*z, no FMA contraction
            float d = __fadd_rn(__fadd_rn(__fmul_rn(dx, dx), __fmul_rn(dy, dy)),
                                __fmul_rn(dz, dz));
            float dd = fminf(sd[i], d);
            sd[i] = dd;
            unsigned long long key =
                ((unsigned long long)__float_as_uint(dd) << 32) |
                (unsigned long long)(0xFFFFFFFFu - (unsigned)i);
            best = best > key ? best : key;
        }
        #pragma unroll
        for (int o = 16; o; o >>= 1) {
            unsigned long long v = __shfl_xor_sync(0xffffffffu, best, o);
            best = best > v ? best : v;
        }
        if ((tid & 31) == 0) wmax[tid >> 5] = best;
        __syncthreads();
        if (tid < 32) {
            unsigned long long v = (tid < 16) ? wmax[tid] : 0ull;
            #pragma unroll
            for (int o = 8; o; o >>= 1) {
                unsigned long long u = __shfl_xor_sync(0xffffffffu, v, o);
                v = v > u ? v : u;
            }
            if (tid == 0) wmax[16] = v;
        }
        __syncthreads();
        last = (int)(0xFFFFFFFFu - (unsigned)(wmax[16] & 0xFFFFFFFFull));
        if (tid == 0) oidx[b * NPOINT + it] = last;
        __syncthreads();
    }
    for (int i = tid; i < NPOINT; i += 512) {
        int id = oidx[b * NPOINT + i];
        octr[(size_t)(b * NPOINT + i) * 3 + 0] = sx[id];
        octr[(size_t)(b * NPOINT + i) * 3 + 1] = sy[id];
        octr[(size_t)(b * NPOINT + i) * 3 + 2] = sz[id];
    }
}

// ---------------- ball query: one warp per center, ordered ballot scan ----------------
template<int N>
__global__ void ballq_kernel(const float* __restrict__ xyz, const float* __restrict__ ctrs,
                             int* __restrict__ out, float rr, int ncent, int S)
{
    int gt = blockIdx.x * blockDim.x + threadIdx.x;
    int gw = gt >> 5, lane = gt & 31;
    if (gw >= ncent) return;
    int b = gw / S;
    const float* p = xyz + (size_t)b * N * 3;
    float cx = ctrs[gw * 3 + 0], cy = ctrs[gw * 3 + 1], cz = ctrs[gw * 3 + 2];
    int* o = out + (size_t)gw * NSAMP;

    int cnt = 0, firstIdx = 0;
    for (int base = 0; base < N; base += 32) {
        int i = base + lane;
        float dx = p[3 * i + 0] - cx;
        float dy = p[3 * i + 1] - cy;
        float dz = p[3 * i + 2] - cz;
        float d = __fadd_rn(__fadd_rn(__fmul_rn(dx, dx), __fmul_rn(dy, dy)),
                            __fmul_rn(dz, dz));
        bool isin = d < rr;
        unsigned m = __ballot_sync(0xffffffffu, isin);
        if (m) {
            if (cnt == 0) firstIdx = base + __ffs(m) - 1;
            int pos = cnt + __popc(m & ((1u << lane) - 1u));
            if (isin && pos < NSAMP) o[pos] = i;
            cnt += __popc(m);
            if (cnt >= NSAMP) break;
        }
    }
    for (int j = cnt + lane; j < NSAMP; j += 32) o[j] = firstIdx;
}

// ---------------- SA1 grouped MLP: 3->64->64->128, maxpool over 64 samples ----------------
// 4 centers per block (amortize weight staging), 256 threads.
__global__ __launch_bounds__(256, 2) void mlp1_kernel(
    const float* __restrict__ xyz, const int* __restrict__ ball,
    const float* __restrict__ ctrs,
    const float* __restrict__ w1, const float* __restrict__ g1, const float* __restrict__ b1,
    const float* __restrict__ w2, const float* __restrict__ g2, const float* __restrict__ b2,
    const float* __restrict__ w3, const float* __restrict__ g3, const float* __restrict__ b3,
    float* __restrict__ feat_out)
{
    extern __shared__ float sm[];
    float* w1s = sm;            // 3*64
    float* w2s = sm + 192;      // 64*64
    float* w3s = sm + 4288;     // 64*128
    float* gb  = sm + 12480;    // 512: g1 b1 g2 b2 g3 b3
    float* xs  = sm + 12992;    // 64*3
    float* h1  = sm + 13184;    // 64*65
    float* h2  = sm + 17344;    // 64*65
    float* m3  = sm + 21504;    // 128

    const int tid = threadIdx.x;
    for (int i = tid; i < 192;  i += 256) w1s[i] = w1[i];
    for (int i = tid; i < 4096; i += 256) w2s[i] = w2[i];
    for (int i = tid; i < 8192; i += 256) w3s[i] = w3[i];
    if (tid < 64) { gb[tid] = g1[tid]; gb[64 + tid] = b1[tid];
                    gb[128 + tid] = g2[tid]; gb[192 + tid] = b2[tid]; }
    if (tid < 128) { gb[256 + tid] = g3[tid]; gb[384 + tid] = b3[tid]; }

    const int s = tid & 63, cg = tid >> 6, lane = tid & 31;

    for (int c4 = 0; c4 < 4; ++c4) {
        const int gc = blockIdx.x * 4 + c4;
        const int b  = gc >> 9;
        __syncthreads();   // orders weight loads / previous-center readers
        if (tid < 64) {
            int pi = ball[(size_t)gc * NSAMP + tid];
            const float* pp = xyz + (size_t)(b * NPTS + pi) * 3;
            xs[tid * 3 + 0] = pp[0] - ctrs[gc * 3 + 0];
            xs[tid * 3 + 1] = pp[1] - ctrs[gc * 3 + 1];
            xs[tid * 3 + 2] = pp[2] - ctrs[gc * 3 + 2];
        }
        if (tid < 128) m3[tid] = 0.f;
        __syncthreads();

        // layer1: 3 -> 64, 16 channels per thread
        {
            const int c0 = cg * 16;
            float x0 = xs[s * 3 + 0], x1 = xs[s * 3 + 1], x2 = xs[s * 3 + 2];
            #pragma unroll
            for (int j = 0; j < 16; ++j) {
                float v = x0 * w1s[c0 + j];
                v = fmaf(x1, w1s[64 + c0 + j], v);
                v = fmaf(x2, w1s[128 + c0 + j], v);
                h1[s * 65 + c0 + j] = fmaxf(fmaf(v, gb[c0 + j], gb[64 + c0 + j]), 0.f);
            }
        }
        __syncthreads();

        // layer2: 64 -> 64
        {
            const int c0 = cg * 16;
            float a[16];
            #pragma unroll
            for (int j = 0; j < 16; ++j) a[j] = 0.f;
            for (int k = 0; k < 64; ++k) {
                float xv = h1[s * 65 + k];
                const float4* wr = (const float4*)(w2s + (k << 6) + c0);
                #pragma unroll
                for (int j = 0; j < 4; ++j) {
                    float4 w4 = wr[j];
                    a[4 * j + 0] = fmaf(xv, w4.x, a[4 * j + 0]);
                    a[4 * j + 1] = fmaf(xv, w4.y, a[4 * j + 1]);
                    a[4 * j + 2] = fmaf(xv, w4.z, a[4 * j + 2]);
                    a[4 * j + 3] = fmaf(xv, w4.w, a[4 * j + 3]);
                }
            }
            #pragma unroll
            for (int j = 0; j < 16; ++j)
                h2[s * 65 + c0 + j] =
                    fmaxf(fmaf(a[j], gb[128 + c0 + j], gb[192 + c0 + j]), 0.f);
        }
        __syncthreads();

        // layer3: 64 -> 128, then maxpool over samples
        {
            const int c0 = cg * 32;
            float a[32];
            #pragma unroll
            for (int j = 0; j < 32; ++j) a[j] = 0.f;
            for (int k = 0; k < 64; ++k) {
                float xv = h2[s * 65 + k];
                const float4* wr = (const float4*)(w3s + (k << 7) + c0);
                #pragma unroll
                for (int j = 0; j < 8; ++j) {
                    float4 w4 = wr[j];
                    a[4 * j + 0] = fmaf(xv, w4.x, a[4 * j + 0]);
                    a[4 * j + 1] = fmaf(xv, w4.y, a[4 * j + 1]);
                    a[4 * j + 2] = fmaf(xv, w4.z, a[4 * j + 2]);
                    a[4 * j + 3] = fmaf(xv, w4.w, a[4 * j + 3]);
                }
            }
            #pragma unroll
            for (int j = 0; j < 32; ++j) {
                float y = fmaxf(fmaf(a[j], gb[256 + c0 + j], gb[384 + c0 + j]), 0.f);
                #pragma unroll
                for (int o = 16; o; o >>= 1)
                    y = fmaxf(y, __shfl_xor_sync(0xffffffffu, y, o));
                if (lane == 0) atomicMax((int*)(m3 + c0 + j), __float_as_int(y));
            }
        }
        __syncthreads();
        if (tid < 128) feat_out[(size_t)gc * 128 + tid] = m3[tid];
    }
}

// ---------------- SA2 grouped MLP: 131->128->128->256, maxpool over 64 ----------------
template<int COUT>
__device__ __forceinline__ void mlp2_layer(
    const float* __restrict__ W, const float* __restrict__ G, const float* __restrict__ Bb,
    const float* ins, int istr, float* outs, int ostr,
    float* wt, float* m3, int K, int tid)
{
    const int s = tid & 63, cg = tid >> 6, lane = tid & 31;
    const int c0 = cg * (COUT / 4);
    const float* irow = ins + s * istr;
    float a[COUT / 4];
    #pragma unroll
    for (int j = 0; j < COUT / 4; ++j) a[j] = 0.f;

    for (int kt = 0; kt < K; kt += 32) {
        const int kw = min(32, K - kt);
        __syncthreads();
        {
            int nv = (kw * COUT) >> 2;
            const float4* src = (const float4*)(W + (size_t)kt * COUT);
            float4* dst = (float4*)wt;
            for (int i = tid; i < nv; i += 256) dst[i] = src[i];
        }
        __syncthreads();
        for (int k = 0; k < kw; ++k) {
            float xv = irow[kt + k];
            const float4* wr = (const float4*)(wt + k * COUT + c0);
            #pragma unroll
            for (int j = 0; j < COUT / 16; ++j) {
                float4 w4 = wr[j];
                a[4 * j + 0] = fmaf(xv, w4.x, a[4 * j + 0]);
                a[4 * j + 1] = fmaf(xv, w4.y, a[4 * j + 1]);
                a[4 * j + 2] = fmaf(xv, w4.z, a[4 * j + 2]);
                a[4 * j + 3] = fmaf(xv, w4.w, a[4 * j + 3]);
            }
        }
    }
    if (m3) {
        #pragma unroll
        for (int j = 0; j < COUT / 4; ++j) {
            float y = fmaxf(fmaf(a[j], __ldg(G + c0 + j), __ldg(Bb + c0 + j)), 0.f);
            #pragma unroll
            for (int o = 16; o; o >>= 1)
                y = fmaxf(y, __shfl_xor_sync(0xffffffffu, y, o));
            if (lane == 0) atomicMax((int*)(m3 + c0 + j), __float_as_int(y));
        }
    } else {
        float* orow = outs + s * ostr;
        #pragma unroll
        for (int j = 0; j < COUT / 4; ++j)
            orow[c0 + j] = fmaxf(fmaf(a[j], __ldg(G + c0 + j), __ldg(Bb + c0 + j)), 0.f);
    }
}

__global__ __launch_bounds__(256) void mlp2_kernel(
    const float* __restrict__ xyz1, const float* __restrict__ feat1,
    const float* __restrict__ ctrs, const int* __restrict__ ball,
    const float* __restrict__ w1, const float* __restrict__ g1, const float* __restrict__ b1,
    const float* __restrict__ w2, const float* __restrict__ g2, const float* __restrict__ b2,
    const float* __restrict__ w3, const float* __restrict__ g3, const float* __restrict__ b3,
    float* __restrict__ feat_out)
{
    extern __shared__ float sm[];
    float* xs = sm;               // 64*137 (reused as h2)
    float* h1 = sm + 8768;        // 64*129
    float* wt = sm + 17024;       // 32*256
    float* m3 = sm + 25216;       // 256

    const int tid = threadIdx.x;
    const int gc = blockIdx.x;          // 0..4095
    const int b = gc >> 7;
    const float cx = ctrs[gc * 3 + 0], cy = ctrs[gc * 3 + 1], cz = ctrs[gc * 3 + 2];

    // stage grouped input: [64 samples][131] = rel-xyz(3) + feat1(128)
    {
        int s = tid >> 2, q = tid & 3;
        int pi = ball[(size_t)gc * NSAMP + s];
        const float4* fr = (const float4*)(feat1 + (size_t)((b << 9) + pi) * 128) + q * 8;
        float* xrow = xs + s * 137;
        if (q == 0) {
            const float* pp = xyz1 + (size_t)((b << 9) + pi) * 3;
            xrow[0] = pp[0] - cx; xrow[1] = pp[1] - cy; xrow[2] = pp[2] - cz;
        }
        #pragma unroll
        for (int i = 0; i < 8; ++i) {
            float4 v = fr[i];
            float* d = xrow + 3 + q * 32 + i * 4;
            d[0] = v.x; d[1] = v.y; d[2] = v.z; d[3] = v.w;
        }
    }
    m3[tid] = 0.f;

    mlp2_layer<128>(w1, g1, b1, xs, 137, h1, 129, wt, nullptr, 131, tid);
    mlp2_layer<128>(w2, g2, b2, h1, 129, xs, 137, wt, nullptr, 128, tid);   // h2 reuses xs
    mlp2_layer<256>(w3, g3, b3, xs, 137, nullptr, 0, wt, m3, 128, tid);
    __syncthreads();
    feat_out[(size_t)gc * 256 + tid] = m3[tid];
}

// ---------------- SA3 head GEMMs ----------------
// MODE 0: plain A. MODE 1: virtual A = concat(xyz2, feat2). MODE 2: plain A + max-reduce into (B,1024).
template<int MODE>
__global__ __launch_bounds__(256) void gemm_kernel(
    const float* __restrict__ A, const float* __restrict__ vx, const float* __restrict__ vf,
    const float* __restrict__ W, const float* __restrict__ G, const float* __restrict__ Bb,
    float* __restrict__ out, int K, int COUT)
{
    __shared__ __align__(16) float At[64 * 33];
    __shared__ __align__(16) float Wt[32 * 64];
    const int tid = threadIdx.x;
    const int r0 = blockIdx.x * 64, cb = blockIdx.y * 64;
    const int r = tid & 63, cg = tid >> 6, c0 = cg * 16, lane = tid & 31;
    float a[16];
    #pragma unroll
    for (int j = 0; j < 16; ++j) a[j] = 0.f;

    for (int kt = 0; kt < K; kt += 32) {
        __syncthreads();
        for (int i = tid; i < 64 * 32; i += 256) {
            int rr = i >> 5, kk = i & 31, kg = kt + kk;
            float v = 0.f;
            if (kg < K) {
                if (MODE == 1)
                    v = (kg < 3) ? vx[(size_t)(r0 + rr) * 3 + kg]
                                 : vf[(size_t)(r0 + rr) * 256 + (kg - 3)];
                else
                    v = A[(size_t)(r0 + rr) * K + kg];
            }
            At[rr * 33 + kk] = v;
        }
        for (int i = tid; i < 32 * 64; i += 256) {
            int kk = i >> 6, cc = i & 63, kg = kt + kk;
            Wt[i] = (kg < K) ? W[(size_t)kg * COUT + cb + cc] : 0.f;
        }
        __syncthreads();
        for (int k = 0; k < 32; ++k) {
            float xv = At[r * 33 + k];
            const float4* wr = (const float4*)(Wt + (k << 6) + c0);
            #pragma unroll
            for (int j = 0; j < 4; ++j) {
                float4 w4 = wr[j];
                a[4 * j + 0] = fmaf(xv, w4.x, a[4 * j + 0]);
                a[4 * j + 1] = fmaf(xv, w4.y, a[4 * j + 1]);
                a[4 * j + 2] = fmaf(xv, w4.z, a[4 * j + 2]);
                a[4 * j + 3] = fmaf(xv, w4.w, a[4 * j + 3]);
            }
        }
    }

    if (MODE == 2) {
        const int b = r0 >> 7;   // 128 rows per batch; 64-row tile stays inside one batch
        #pragma unroll
        for (int j = 0; j < 16; ++j) {
            float y = fmaxf(fmaf(a[j], __ldg(G + cb + c0 + j), __ldg(Bb + cb + c0 + j)), 0.f);
            #pragma unroll
            for (int o = 16; o; o >>= 1)
                y = fmaxf(y, __shfl_xor_sync(0xffffffffu, y, o));
            if (lane == 0)
                atomicMax((int*)(out + (size_t)b * 1024 + cb + c0 + j), __float_as_int(y));
        }
    } else {
        #pragma unroll
        for (int j = 0; j < 16; ++j)
            a[j] = fmaxf(fmaf(a[j], __ldg(G + cb + c0 + j), __ldg(Bb + cb + c0 + j)), 0.f);
        float4* op = (float4*)(out + (size_t)(r0 + r) * COUT + cb + c0);
        op[0] = make_float4(a[0], a[1], a[2], a[3]);
        op[1] = make_float4(a[4], a[5], a[6], a[7]);
        op[2] = make_float4(a[8], a[9], a[10], a[11]);
        op[3] = make_float4(a[12], a[13], a[14], a[15]);
    }
}

__global__ void zero_kernel(float* o, int n)
{
    int i = blockIdx.x * blockDim.x + threadIdx.x;
    if (i < n) o[i] = 0.f;
}

// ---------------- launch ----------------
extern "C" void kernel_launch(void* const* d_in, const int* in_sizes, int n_in,
                              void* d_out, int out_size)
{
    const float* pc  = (const float*)d_in[0];
    const float* w10 = (const float*)d_in[1];
    const float* g10 = (const float*)d_in[2];
    const float* b10 = (const float*)d_in[3];
    const float* w11 = (const float*)d_in[4];
    const float* g11 = (const float*)d_in[5];
    const float* b11 = (const float*)d_in[6];
    const float* w12 = (const float*)d_in[7];
    const float* g12 = (const float*)d_in[8];
    const float* b12 = (const float*)d_in[9];
    const float* w20 = (const float*)d_in[10];
    const float* g20 = (const float*)d_in[11];
    const float* b20 = (const float*)d_in[12];
    const float* w21 = (const float*)d_in[13];
    const float* g21 = (const float*)d_in[14];
    const float* b21 = (const float*)d_in[15];
    const float* w22 = (const float*)d_in[16];
    const float* g22 = (const float*)d_in[17];
    const float* b22 = (const float*)d_in[18];
    const float* w30 = (const float*)d_in[19];
    const float* g30 = (const float*)d_in[20];
    const float* b30 = (const float*)d_in[21];
    const float* w31 = (const float*)d_in[22];
    const float* g31 = (const float*)d_in[23];
    const float* b31 = (const float*)d_in[24];
    const float* w32 = (const float*)d_in[25];
    const float* g32 = (const float*)d_in[26];
    const float* b32 = (const float*)d_in[27];
    float* out = (float*)d_out;

    void *pf = nullptr, *pi = nullptr;
    cudaGetSymbolAddress(&pf, d_fscratch);
    cudaGetSymbolAddress(&pi, d_iscratch);
    float* fs = (float*)pf;
    int*   is = (int*)pi;

    float* xyz1  = fs + OFF_XYZ1;
    float* feat1 = fs + OFF_FEAT1;
    float* xyz2  = fs + OFF_XYZ2;
    float* feat2 = fs + OFF_FEAT2;
    float* h31   = fs + OFF_H31;
    float* h32   = fs + OFF_H32;
    int* fps1  = is + IOFF_FPS1;
    int* ball1 = is + IOFF_BALL1;
    int* fps2  = is + IOFF_FPS2;
    int* ball2 = is + IOFF_BALL2;

    cudaFuncSetAttribute(fps_kernel<NPTS, S1>,
                         cudaFuncAttributeMaxDynamicSharedMemorySize, NPTS * 4 * 4);
    cudaFuncSetAttribute(mlp1_kernel,
                         cudaFuncAttributeMaxDynamicSharedMemorySize, 21632 * 4);
    cudaFuncSetAttribute(mlp2_kernel,
                         cudaFuncAttributeMaxDynamicSharedMemorySize, 25472 * 4);

    const float rr1 = (float)(0.2 * 0.2);   // match JAX: double product cast to f32
    const float rr2 = (float)(0.4 * 0.4);

    // SA1
    fps_kernel<NPTS, S1><<<BB, 512, NPTS * 4 * 4>>>(pc, fps1, xyz1);
    {
        int ncent = BB * S1;
        int blocks = (ncent * 32 + 255) / 256;
        ballq_kernel<NPTS><<<blocks, 256>>>(pc, xyz1, ball1, rr1, ncent, S1);
    }
    mlp1_kernel<<<BB * S1 / 4, 256, 21632 * 4>>>(pc, ball1, xyz1,
        w10, g10, b10, w11, g11, b11, w12, g12, b12, feat1);

    // SA2
    fps_kernel<S1, S2><<<BB, 512, S1 * 4 * 4>>>(xyz1, fps2, xyz2);
    {
        int ncent = BB * S2;
        int blocks = (ncent * 32 + 255) / 256;
        ballq_kernel<S1><<<blocks, 256>>>(xyz1, xyz2, ball2, rr2, ncent, S2);
    }
    mlp2_kernel<<<BB * S2, 256, 25472 * 4>>>(xyz1, feat1, xyz2, ball2,
        w20, g20, b20, w21, g21, b21, w22, g22, b22, feat2);

    // SA3 head: (B*128, 259) -> 256 -> 512 -> 1024, max over 128 -> (B,1024)
    gemm_kernel<1><<<dim3(BB * S2 / 64, 256 / 64), 256>>>(
        nullptr, xyz2, feat2, w30, g30, b30, h31, 259, 256);
    gemm_kernel<0><<<dim3(BB * S2 / 64, 512 / 64), 256>>>(
        h31, nullptr, nullptr, w31, g31, b31, h32, 256, 512);
    zero_kernel<<<(BB * 1024 + 255) / 256, 256>>>(out, BB * 1024);
    gemm_kernel<2><<<dim3(BB * S2 / 64, 1024 / 64), 256>>>(
        h32, nullptr, nullptr, w32, g32, b32, out, 512, 1024);
}

// round 5
// speedup vs baseline: 1.0352x; 1.0352x over previous
#include <cuda_runtime.h>
#include <cstdint>

#define BB 32
#define NPTS 4096
#define S1 512
#define S2 128
#define NSAMP 64

// ---------------- scratch (static device memory; no allocation) ----------------
#define OFF_XYZ1  0                        // 32*512*3
#define OFF_FEAT1 (OFF_XYZ1 + BB*S1*3)     // 32*512*128
#define OFF_XYZ2  (OFF_FEAT1 + BB*S1*128)  // 32*128*3
#define OFF_FEAT2 (OFF_XYZ2 + BB*S2*3)     // 32*128*256
#define OFF_H31   (OFF_FEAT2 + BB*S2*256)  // 32*128*256
#define OFF_H32   (OFF_H31 + BB*S2*256)    // 32*128*512
#define FSCRATCH_TOTAL (OFF_H32 + BB*S2*512)

#define IOFF_BALL1 0
#define IOFF_BALL2 (IOFF_BALL1 + BB*S1*NSAMP)
#define ISCRATCH_TOTAL (IOFF_BALL2 + BB*S2*NSAMP)

__device__ float d_fscratch[FSCRATCH_TOTAL];
__device__ int   d_iscratch[ISCRATCH_TOTAL];

// ---------------- packed f32x2 helpers (Blackwell fma.rn.f32x2) ----------------
__device__ __forceinline__ void fma2(unsigned long long& d,
                                     unsigned long long a, unsigned long long b)
{
    asm("fma.rn.f32x2 %0, %1, %2, %0;" : "+l"(d) : "l"(a), "l"(b));
}
__device__ __forceinline__ unsigned long long pack2(float x)
{
    unsigned long long r; unsigned u = __float_as_uint(x);
    asm("mov.b64 %0, {%1, %1};" : "=l"(r) : "r"(u));
    return r;
}
__device__ __forceinline__ float2 unpack2(unsigned long long v)
{
    unsigned lo, hi;
    asm("mov.b64 {%0, %1}, %2;" : "=r"(lo), "=r"(hi) : "l"(v));
    return make_float2(__uint_as_float(lo), __uint_as_float(hi));
}

// ---------------- FPS (big): 512 threads, dist in registers, 1 barrier/iter ----------------
template<int N, int NPOINT>
__global__ void fps_kernel(const float* __restrict__ xyz, float* __restrict__ octr)
{
    constexpr int NT = 512;
    constexpr int PT = N / NT;
    extern __shared__ float smf[];
    float* sx = smf;
    float* sy = smf + N;
    float* sz = smf + 2 * N;
    int* sidx = (int*)(smf + 3 * N);
    __shared__ unsigned long long wmax[2][NT / 32];

    const int b = blockIdx.x, tid = threadIdx.x;
    const int lane = tid & 31, warp = tid >> 5;
    const float* p = xyz + (size_t)b * N * 3;

    for (int i = tid; i < N; i += NT) {
        sx[i] = p[3 * i + 0];
        sy[i] = p[3 * i + 1];
        sz[i] = p[3 * i + 2];
    }
    float pd[PT];
    #pragma unroll
    for (int j = 0; j < PT; ++j) pd[j] = 1e10f;
    if (tid == 0) sidx[0] = 0;
    __syncthreads();

    int last = 0;
    for (int it = 1; it < NPOINT; ++it) {
        const float lx = sx[last], ly = sy[last], lz = sz[last];
        unsigned long long best = 0ull;
        #pragma unroll
        for (int j = 0; j < PT; ++j) {
            int i = tid + j * NT;
            float dx = sx[i] - lx, dy = sy[i] - ly, dz = sz[i] - lz;
            // exact reference arithmetic: (x*x + y*y) + z*z, no FMA contraction
            float d = __fadd_rn(__fadd_rn(__fmul_rn(dx, dx), __fmul_rn(dy, dy)),
                                __fmul_rn(dz, dz));
            float dd = fminf(pd[j], d);
            pd[j] = dd;
            unsigned long long key =
                ((unsigned long long)__float_as_uint(dd) << 32) |
                (unsigned long long)(0xFFFFFFFFu - (unsigned)i);
            best = best > key ? best : key;
        }
        #pragma unroll
        for (int o = 16; o; o >>= 1) {
            unsigned long long v = __shfl_xor_sync(0xffffffffu, best, o);
            best = best > v ? best : v;
        }
        if (lane == 0) wmax[it & 1][warp] = best;
        __syncthreads();
        // redundant per-warp reduce of the 16 partials (no second barrier;
        // double-buffered wmax prevents next-iter overwrite hazard)
        unsigned long long v = (lane < NT / 32) ? wmax[it & 1][lane] : 0ull;
        #pragma unroll
        for (int o = 16; o; o >>= 1) {
            unsigned long long u = __shfl_xor_sync(0xffffffffu, v, o);
            v = v > u ? v : u;
        }
        last = (int)(0xFFFFFFFFu - (unsigned)(v & 0xFFFFFFFFull));
        if (tid == 0) sidx[it] = last;
    }
    __syncthreads();
    for (int i = tid; i < NPOINT; i += NT) {
        int id = sidx[i];
        octr[(size_t)(b * NPOINT + i) * 3 + 0] = sx[id];
        octr[(size_t)(b * NPOINT + i) * 3 + 1] = sy[id];
        octr[(size_t)(b * NPOINT + i) * 3 + 2] = sz[id];
    }
}

// ---------------- FPS (small): one warp per batch, zero barriers ----------------
__global__ void fps_small_kernel(const float* __restrict__ xyz, float* __restrict__ octr)
{
    __shared__ float sx[S1], sy[S1], sz[S1];
    __shared__ int sidx[S2];
    const int b = blockIdx.x, lane = threadIdx.x;
    const float* p = xyz + (size_t)b * S1 * 3;

    for (int i = lane; i < S1; i += 32) {
        sx[i] = p[3 * i + 0];
        sy[i] = p[3 * i + 1];
        sz[i] = p[3 * i + 2];
    }
    float pd[S1 / 32];
    #pragma unroll
    for (int j = 0; j < S1 / 32; ++j) pd[j] = 1e10f;
    if (lane == 0) sidx[0] = 0;
    __syncwarp();

    int last = 0;
    for (int it = 1; it < S2; ++it) {
        const float lx = sx[last], ly = sy[last], lz = sz[last];
        unsigned long long best = 0ull;
        #pragma unroll
        for (int j = 0; j < S1 / 32; ++j) {
            int i = lane + j * 32;
            float dx = sx[i] - lx, dy = sy[i] - ly, dz = sz[i] - lz;
            float d = __fadd_rn(__fadd_rn(__fmul_rn(dx, dx), __fmul_rn(dy, dy)),
                                __fmul_rn(dz, dz));
            float dd = fminf(pd[j], d);
            pd[j] = dd;
            unsigned long long key =
                ((unsigned long long)__float_as_uint(dd) << 32) |
                (unsigned long long)(0xFFFFFFFFu - (unsigned)i);
            best = best > key ? best : key;
        }
        #pragma unroll
        for (int o = 16; o; o >>= 1) {
            unsigned long long v = __shfl_xor_sync(0xffffffffu, best, o);
            best = best > v ? best : v;
        }
        last = (int)(0xFFFFFFFFu - (unsigned)(best & 0xFFFFFFFFull));
        if (lane == 0) sidx[it] = last;
    }
    __syncwarp();
    for (int i = lane; i < S2; i += 32) {
        int id = sidx[i];
        octr[(size_t)(b * S2 + i) * 3 + 0] = sx[id];
        octr[(size_t)(b * S2 + i) * 3 + 1] = sy[id];
        octr[(size_t)(b * S2 + i) * 3 + 2] = sz[id];
    }
}

// ---------------- ball query: one warp per center, ordered ballot scan ----------------
template<int N>
__global__ void ballq_kernel(const float* __restrict__ xyz, const float* __restrict__ ctrs,
                             int* __restrict__ out, float rr, int ncent, int S)
{
    int gt = blockIdx.x * blockDim.x + threadIdx.x;
    int gw = gt >> 5, lane = gt & 31;
    if (gw >= ncent) return;
    int b = gw / S;
    const float* p = xyz + (size_t)b * N * 3;
    float cx = ctrs[gw * 3 + 0], cy = ctrs[gw * 3 + 1], cz = ctrs[gw * 3 + 2];
    int* o = out + (size_t)gw * NSAMP;

    int cnt = 0, firstIdx = 0;
    for (int base = 0; base < N; base += 32) {
        int i = base + lane;
        float dx = p[3 * i + 0] - cx;
        float dy = p[3 * i + 1] - cy;
        float dz = p[3 * i + 2] - cz;
        float d = __fadd_rn(__fadd_rn(__fmul_rn(dx, dx), __fmul_rn(dy, dy)),
                            __fmul_rn(dz, dz));
        bool isin = d < rr;
        unsigned m = __ballot_sync(0xffffffffu, isin);
        if (m) {
            if (cnt == 0) firstIdx = base + __ffs(m) - 1;
            int pos = cnt + __popc(m & ((1u << lane) - 1u));
            if (isin && pos < NSAMP) o[pos] = i;
            cnt += __popc(m);
            if (cnt >= NSAMP) break;
        }
    }
    for (int j = cnt + lane; j < NSAMP; j += 32) o[j] = firstIdx;
}

// ---------------- SA1 grouped MLP: 3->64->64->128, maxpool, f32x2 FMAs ----------------
__global__ __launch_bounds__(256, 2) void mlp1_kernel(
    const float* __restrict__ xyz, const int* __restrict__ ball,
    const float* __restrict__ ctrs,
    const float* __restrict__ w1, const float* __restrict__ g1, const float* __restrict__ b1,
    const float* __restrict__ w2, const float* __restrict__ g2, const float* __restrict__ b2,
    const float* __restrict__ w3, const float* __restrict__ g3, const float* __restrict__ b3,
    float* __restrict__ feat_out)
{
    extern __shared__ float sm[];
    float* w1s = sm;            // 3*64
    float* w2s = sm + 192;      // 64*64
    float* w3s = sm + 4288;     // 64*128
    float* gb  = sm + 12480;    // 512: g1 b1 g2 b2 g3 b3
    float* xs  = sm + 12992;    // 64*3
    float* h1  = sm + 13184;    // 64*65
    float* h2  = sm + 17344;    // 64*65
    float* m3  = sm + 21504;    // 128

    const int tid = threadIdx.x;
    for (int i = tid; i < 192;  i += 256) w1s[i] = w1[i];
    for (int i = tid; i < 4096; i += 256) w2s[i] = w2[i];
    for (int i = tid; i < 8192; i += 256) w3s[i] = w3[i];
    if (tid < 64) { gb[tid] = g1[tid]; gb[64 + tid] = b1[tid];
                    gb[128 + tid] = g2[tid]; gb[192 + tid] = b2[tid]; }
    if (tid < 128) { gb[256 + tid] = g3[tid]; gb[384 + tid] = b3[tid]; }

    const int s = tid & 63, cg = tid >> 6, lane = tid & 31;

    for (int c4 = 0; c4 < 4; ++c4) {
        const int gc = blockIdx.x * 4 + c4;
        const int b  = gc >> 9;
        __syncthreads();   // orders weight loads / previous-center readers
        if (tid < 64) {
            int pi = ball[(size_t)gc * NSAMP + tid];
            const float* pp = xyz + (size_t)(b * NPTS + pi) * 3;
            xs[tid * 3 + 0] = pp[0] - ctrs[gc * 3 + 0];
            xs[tid * 3 + 1] = pp[1] - ctrs[gc * 3 + 1];
            xs[tid * 3 + 2] = pp[2] - ctrs[gc * 3 + 2];
        }
        if (tid < 128) m3[tid] = 0.f;
        __syncthreads();

        // layer1: 3 -> 64, 16 channels per thread
        {
            const int c0 = cg * 16;
            float x0 = xs[s * 3 + 0], x1 = xs[s * 3 + 1], x2 = xs[s * 3 + 2];
            #pragma unroll
            for (int j = 0; j < 16; ++j) {
                float v = x0 * w1s[c0 + j];
                v = fmaf(x1, w1s[64 + c0 + j], v);
                v = fmaf(x2, w1s[128 + c0 + j], v);
                h1[s * 65 + c0 + j] = fmaxf(fmaf(v, gb[c0 + j], gb[64 + c0 + j]), 0.f);
            }
        }
        __syncthreads();

        // layer2: 64 -> 64, packed f32x2
        {
            const int c0 = cg * 16;
            unsigned long long a2[8];
            #pragma unroll
            for (int j = 0; j < 8; ++j) a2[j] = 0ull;
            for (int k = 0; k < 64; ++k) {
                unsigned long long xv2 = pack2(h1[s * 65 + k]);
                const ulonglong2* wr = (const ulonglong2*)(w2s + (k << 6) + c0);
                #pragma unroll
                for (int j = 0; j < 4; ++j) {
                    ulonglong2 w = wr[j];
                    fma2(a2[2 * j + 0], xv2, w.x);
                    fma2(a2[2 * j + 1], xv2, w.y);
                }
            }
            #pragma unroll
            for (int j = 0; j < 8; ++j) {
                float2 v = unpack2(a2[j]);
                int c = c0 + 2 * j;
                h2[s * 65 + c + 0] = fmaxf(fmaf(v.x, gb[128 + c + 0], gb[192 + c + 0]), 0.f);
                h2[s * 65 + c + 1] = fmaxf(fmaf(v.y, gb[128 + c + 1], gb[192 + c + 1]), 0.f);
            }
        }
        __syncthreads();

        // layer3: 64 -> 128 (packed), then maxpool over samples
        {
            const int c0 = cg * 32;
            unsigned long long a2[16];
            #pragma unroll
            for (int j = 0; j < 16; ++j) a2[j] = 0ull;
            for (int k = 0; k < 64; ++k) {
                unsigned long long xv2 = pack2(h2[s * 65 + k]);
                const ulonglong2* wr = (const ulonglong2*)(w3s + (k << 7) + c0);
                #pragma unroll
                for (int j = 0; j < 8; ++j) {
                    ulonglong2 w = wr[j];
                    fma2(a2[2 * j + 0], xv2, w.x);
                    fma2(a2[2 * j + 1], xv2, w.y);
                }
            }
            #pragma unroll
            for (int j = 0; j < 16; ++j) {
                float2 v = unpack2(a2[j]);
                int c = c0 + 2 * j;
                float y0 = fmaxf(fmaf(v.x, gb[256 + c + 0], gb[384 + c + 0]), 0.f);
                float y1 = fmaxf(fmaf(v.y, gb[256 + c + 1], gb[384 + c + 1]), 0.f);
                #pragma unroll
                for (int o = 16; o; o >>= 1) {
                    y0 = fmaxf(y0, __shfl_xor_sync(0xffffffffu, y0, o));
                    y1 = fmaxf(y1, __shfl_xor_sync(0xffffffffu, y1, o));
                }
                if (lane == 0) {
                    atomicMax((int*)(m3 + c + 0), __float_as_int(y0));
                    atomicMax((int*)(m3 + c + 1), __float_as_int(y1));
                }
            }
        }
        __syncthreads();
        if (tid < 128) feat_out[(size_t)gc * 128 + tid] = m3[tid];
    }
}

// ---------------- SA2 grouped MLP: 131->128->128->256, maxpool, f32x2 ----------------
template<int COUT>
__device__ __forceinline__ void mlp2_layer(
    const float* __restrict__ W, const float* __restrict__ G, const float* __restrict__ Bb,
    const float* ins, int istr, float* outs, int ostr,
    float* wt, float* m3, int K, int tid)
{
    const int s = tid & 63, cg = tid >> 6, lane = tid & 31;
    const int c0 = cg * (COUT / 4);
    const float* irow = ins + s * istr;
    unsigned long long a2[COUT / 8];
    #pragma unroll
    for (int j = 0; j < COUT / 8; ++j) a2[j] = 0ull;

    for (int kt = 0; kt < K; kt += 32) {
        const int kw = min(32, K - kt);
        __syncthreads();
        {
            int nv = (kw * COUT) >> 2;
            const float4* src = (const float4*)(W + (size_t)kt * COUT);
            float4* dst = (float4*)wt;
            for (int i = tid; i < nv; i += 256) dst[i] = src[i];
        }
        __syncthreads();
        for (int k = 0; k < kw; ++k) {
            unsigned long long xv2 = pack2(irow[kt + k]);
            const ulonglong2* wr = (const ulonglong2*)(wt + k * COUT + c0);
            #pragma unroll
            for (int j = 0; j < COUT / 16; ++j) {
                ulonglong2 w = wr[j];
                fma2(a2[2 * j + 0], xv2, w.x);
                fma2(a2[2 * j + 1], xv2, w.y);
            }
        }
    }
    if (m3) {
        #pragma unroll
        for (int j = 0; j < COUT / 8; ++j) {
            float2 v = unpack2(a2[j]);
            int c = c0 + 2 * j;
            float y0 = fmaxf(fmaf(v.x, __ldg(G + c + 0), __ldg(Bb + c + 0)), 0.f);
            float y1 = fmaxf(fmaf(v.y, __ldg(G + c + 1), __ldg(Bb + c + 1)), 0.f);
            #pragma unroll
            for (int o = 16; o; o >>= 1) {
                y0 = fmaxf(y0, __shfl_xor_sync(0xffffffffu, y0, o));
                y1 = fmaxf(y1, __shfl_xor_sync(0xffffffffu, y1, o));
            }
            if (lane == 0) {
                atomicMax((int*)(m3 + c + 0), __float_as_int(y0));
                atomicMax((int*)(m3 + c + 1), __float_as_int(y1));
            }
        }
    } else {
        float* orow = outs + s * ostr;
        #pragma unroll
        for (int j = 0; j < COUT / 8; ++j) {
            float2 v = unpack2(a2[j]);
            int c = c0 + 2 * j;
            orow[c + 0] = fmaxf(fmaf(v.x, __ldg(G + c + 0), __ldg(Bb + c + 0)), 0.f);
            orow[c + 1] = fmaxf(fmaf(v.y, __ldg(G + c + 1), __ldg(Bb + c + 1)), 0.f);
        }
    }
}

__global__ __launch_bounds__(256) void mlp2_kernel(
    const float* __restrict__ xyz1, const float* __restrict__ feat1,
    const float* __restrict__ ctrs, const int* __restrict__ ball,
    const float* __restrict__ w1, const float* __restrict__ g1, const float* __restrict__ b1,
    const float* __restrict__ w2, const float* __restrict__ g2, const float* __restrict__ b2,
    const float* __restrict__ w3, const float* __restrict__ g3, const float* __restrict__ b3,
    float* __restrict__ feat_out)
{
    extern __shared__ float sm[];
    float* xs = sm;               // 64*137 (reused as h2)
    float* h1 = sm + 8768;        // 64*129
    float* wt = sm + 17024;       // 32*256
    float* m3 = sm + 25216;       // 256

    const int tid = threadIdx.x;
    const int gc = blockIdx.x;          // 0..4095
    const int b = gc >> 7;
    const float cx = ctrs[gc * 3 + 0], cy = ctrs[gc * 3 + 1], cz = ctrs[gc * 3 + 2];

    // stage grouped input: [64 samples][131] = rel-xyz(3) + feat1(128)
    {
        int s = tid >> 2, q = tid & 3;
        int pi = ball[(size_t)gc * NSAMP + s];
        const float4* fr = (const float4*)(feat1 + (size_t)((b << 9) + pi) * 128) + q * 8;
        float* xrow = xs + s * 137;
        if (q == 0) {
            const float* pp = xyz1 + (size_t)((b << 9) + pi) * 3;
            xrow[0] = pp[0] - cx; xrow[1] = pp[1] - cy; xrow[2] = pp[2] - cz;
        }
        #pragma unroll
        for (int i = 0; i < 8; ++i) {
            float4 v = fr[i];
            float* d = xrow + 3 + q * 32 + i * 4;
            d[0] = v.x; d[1] = v.y; d[2] = v.z; d[3] = v.w;
        }
    }
    m3[tid] = 0.f;

    mlp2_layer<128>(w1, g1, b1, xs, 137, h1, 129, wt, nullptr, 131, tid);
    mlp2_layer<128>(w2, g2, b2, h1, 129, xs, 137, wt, nullptr, 128, tid);   // h2 reuses xs
    mlp2_layer<256>(w3, g3, b3, xs, 137, nullptr, 0, wt, m3, 128, tid);
    __syncthreads();
    feat_out[(size_t)gc * 256 + tid] = m3[tid];
}

// ---------------- SA3 head GEMMs (f32x2) ----------------
// MODE 0: plain A. MODE 1: virtual A = concat(xyz2, feat2). MODE 2: plain A + max-reduce into (B,1024).
template<int MODE>
__global__ __launch_bounds__(256) void gemm_kernel(
    const float* __restrict__ A, const float* __restrict__ vx, const float* __restrict__ vf,
    const float* __restrict__ W, const float* __restrict__ G, const float* __restrict__ Bb,
    float* __restrict__ out, int K, int COUT)
{
    __shared__ __align__(16) float At[64 * 33];
    __shared__ __align__(16) float Wt[32 * 64];
    const int tid = threadIdx.x;
    const int r0 = blockIdx.x * 64, cb = blockIdx.y * 64;
    const int r = tid & 63, cg = tid >> 6, c0 = cg * 16, lane = tid & 31;
    unsigned long long a2[8];
    #pragma unroll
    for (int j = 0; j < 8; ++j) a2[j] = 0ull;

    for (int kt = 0; kt < K; kt += 32) {
        __syncthreads();
        for (int i = tid; i < 64 * 32; i += 256) {
            int rr = i >> 5, kk = i & 31, kg = kt + kk;
            float v = 0.f;
            if (kg < K) {
                if (MODE == 1)
                    v = (kg < 3) ? vx[(size_t)(r0 + rr) * 3 + kg]
                                 : vf[(size_t)(r0 + rr) * 256 + (kg - 3)];
                else
                    v = A[(size_t)(r0 + rr) * K + kg];
            }
            At[rr * 33 + kk] = v;
        }
        for (int i = tid; i < 32 * 64; i += 256) {
            int kk = i >> 6, cc = i & 63, kg = kt + kk;
            Wt[i] = (kg < K) ? W[(size_t)kg * COUT + cb + cc] : 0.f;
        }
        __syncthreads();
        for (int k = 0; k < 32; ++k) {
            unsigned long long xv2 = pack2(At[r * 33 + k]);
            const ulonglong2* wr = (const ulonglong2*)(Wt + (k << 6) + c0);
            #pragma unroll
            for (int j = 0; j < 4; ++j) {
                ulonglong2 w = wr[j];
                fma2(a2[2 * j + 0], xv2, w.x);
                fma2(a2[2 * j + 1], xv2, w.y);
            }
        }
    }

    if (MODE == 2) {
        const int b = r0 >> 7;   // 128 rows per batch; 64-row tile stays inside one batch
        #pragma unroll
        for (int j = 0; j < 8; ++j) {
            float2 v = unpack2(a2[j]);
            int c = cb + c0 + 2 * j;
            float y0 = fmaxf(fmaf(v.x, __ldg(G + c + 0), __ldg(Bb + c + 0)), 0.f);
            float y1 = fmaxf(fmaf(v.y, __ldg(G + c + 1), __ldg(Bb + c + 1)), 0.f);
            #pragma unroll
            for (int o = 16; o; o >>= 1) {
                y0 = fmaxf(y0, __shfl_xor_sync(0xffffffffu, y0, o));
                y1 = fmaxf(y1, __shfl_xor_sync(0xffffffffu, y1, o));
            }
            if (lane == 0) {
                atomicMax((int*)(out + (size_t)b * 1024 + c + 0), __float_as_int(y0));
                atomicMax((int*)(out + (size_t)b * 1024 + c + 1), __float_as_int(y1));
            }
        }
    } else {
        float res[16];
        #pragma unroll
        for (int j = 0; j < 8; ++j) {
            float2 v = unpack2(a2[j]);
            int c = cb + c0 + 2 * j;
            res[2 * j + 0] = fmaxf(fmaf(v.x, __ldg(G + c + 0), __ldg(Bb + c + 0)), 0.f);
            res[2 * j + 1] = fmaxf(fmaf(v.y, __ldg(G + c + 1), __ldg(Bb + c + 1)), 0.f);
        }
        float4* op = (float4*)(out + (size_t)(r0 + r) * COUT + cb + c0);
        op[0] = make_float4(res[0], res[1], res[2], res[3]);
        op[1] = make_float4(res[4], res[5], res[6], res[7]);
        op[2] = make_float4(res[8], res[9], res[10], res[11]);
        op[3] = make_float4(res[12], res[13], res[14], res[15]);
    }
}

__global__ void zero_kernel(float* o, int n)
{
    int i = blockIdx.x * blockDim.x + threadIdx.x;
    if (i < n) o[i] = 0.f;
}

// ---------------- launch ----------------
extern "C" void kernel_launch(void* const* d_in, const int* in_sizes, int n_in,
                              void* d_out, int out_size)
{
    const float* pc  = (const float*)d_in[0];
    const float* w10 = (const float*)d_in[1];
    const float* g10 = (const float*)d_in[2];
    const float* b10 = (const float*)d_in[3];
    const float* w11 = (const float*)d_in[4];
    const float* g11 = (const float*)d_in[5];
    const float* b11 = (const float*)d_in[6];
    const float* w12 = (const float*)d_in[7];
    const float* g12 = (const float*)d_in[8];
    const float* b12 = (const float*)d_in[9];
    const float* w20 = (const float*)d_in[10];
    const float* g20 = (const float*)d_in[11];
    const float* b20 = (const float*)d_in[12];
    const float* w21 = (const float*)d_in[13];
    const float* g21 = (const float*)d_in[14];
    const float* b21 = (const float*)d_in[15];
    const float* w22 = (const float*)d_in[16];
    const float* g22 = (const float*)d_in[17];
    const float* b22 = (const float*)d_in[18];
    const float* w30 = (const float*)d_in[19];
    const float* g30 = (const float*)d_in[20];
    const float* b30 = (const float*)d_in[21];
    const float* w31 = (const float*)d_in[22];
    const float* g31 = (const float*)d_in[23];
    const float* b31 = (const float*)d_in[24];
    const float* w32 = (const float*)d_in[25];
    const float* g32 = (const float*)d_in[26];
    const float* b32 = (const float*)d_in[27];
    float* out = (float*)d_out;

    void *pf = nullptr, *pi = nullptr;
    cudaGetSymbolAddress(&pf, d_fscratch);
    cudaGetSymbolAddress(&pi, d_iscratch);
    float* fs = (float*)pf;
    int*   is = (int*)pi;

    float* xyz1  = fs + OFF_XYZ1;
    float* feat1 = fs + OFF_FEAT1;
    float* xyz2  = fs + OFF_XYZ2;
    float* feat2 = fs + OFF_FEAT2;
    float* h31   = fs + OFF_H31;
    float* h32   = fs + OFF_H32;
    int* ball1 = is + IOFF_BALL1;
    int* ball2 = is + IOFF_BALL2;

    const int fps1_smem = 3 * NPTS * 4 + S1 * 4;
    cudaFuncSetAttribute(fps_kernel<NPTS, S1>,
                         cudaFuncAttributeMaxDynamicSharedMemorySize, fps1_smem);
    cudaFuncSetAttribute(mlp1_kernel,
                         cudaFuncAttributeMaxDynamicSharedMemorySize, 21632 * 4);
    cudaFuncSetAttribute(mlp2_kernel,
                         cudaFuncAttributeMaxDynamicSharedMemorySize, 25472 * 4);

    const float rr1 = (float)(0.2 * 0.2);   // match JAX: double product cast to f32
    const float rr2 = (float)(0.4 * 0.4);

    // SA1
    fps_kernel<NPTS, S1><<<BB, 512, fps1_smem>>>(pc, xyz1);
    {
        int ncent = BB * S1;
        int blocks = (ncent * 32 + 255) / 256;
        ballq_kernel<NPTS><<<blocks, 256>>>(pc, xyz1, ball1, rr1, ncent, S1);
    }
    mlp1_kernel<<<BB * S1 / 4, 256, 21632 * 4>>>(pc, ball1, xyz1,
        w10, g10, b10, w11, g11, b11, w12, g12, b12, feat1);

    // SA2
    fps_small_kernel<<<BB, 32>>>(xyz1, xyz2);
    {
        int ncent = BB * S2;
        int blocks = (ncent * 32 + 255) / 256;
        ballq_kernel<S1><<<blocks, 256>>>(xyz1, xyz2, ball2, rr2, ncent, S2);
    }
    mlp2_kernel<<<BB * S2, 256, 25472 * 4>>>(xyz1, feat1, xyz2, ball2,
        w20, g20, b20, w21, g21, b21, w22, g22, b22, feat2);

    // SA3 head: (B*128, 259) -> 256 -> 512 -> 1024, max over 128 -> (B,1024)
    gemm_kernel<1><<<dim3(BB * S2 / 64, 256 / 64), 256>>>(
        nullptr, xyz2, feat2, w30, g30, b30, h31, 259, 256);
    gemm_kernel<0><<<dim3(BB * S2 / 64, 512 / 64), 256>>>(
        h31, nullptr, nullptr, w31, g31, b31, h32, 256, 512);
    zero_kernel<<<(BB * 1024 + 255) / 256, 256>>>(out, BB * 1024);
    gemm_kernel<2><<<dim3(BB * S2 / 64, 1024 / 64), 256>>>(
        h32, nullptr, nullptr, w32, g32, b32, out, 512, 1024);
}